// round 15
// baseline (speedup 1.0000x reference)
#include <cuda_runtime.h>
#include <cuda_bf16.h>
#include <cstdint>

#define NN 50000
#define NE 400000
#define NG 32
#define D  64
#define IND 11
#define EPSB 1e-5f

typedef unsigned long long u64;

#define F2FMA(acc, a, b) asm("fma.rn.f32x2 %0, %1, %2, %0;" : "+l"(acc) : "l"(a), "l"(b))
#define F2ADD(d, a, b)   asm("add.rn.f32x2 %0, %1, %2;" : "=l"(d) : "l"(a), "l"(b))
#define F2BCAST(d, x)    { unsigned _u = __float_as_uint(x); asm("mov.b64 %0, {%1, %1};" : "=l"(d) : "r"(_u)); }
#define F2UNPACK(lo, hi, p) { unsigned _a, _b; asm("mov.b64 {%0, %1}, %2;" : "=r"(_a), "=r"(_b) : "l"(p)); lo = __uint_as_float(_a); hi = __uint_as_float(_b); }

__device__ float g_h[NN*D];
__device__ float g_P[NN*D];
__device__ float g_Q[NN*D];
__device__ __nv_bfloat16 g_y1[NE*D];
__device__ __nv_bfloat16 g_y2[NE*D];
__device__ float g_y3[NN*D];
__device__ float g_y4[NN*D];
__device__ float g_sum[16*64];
__device__ float g_sq[16*64];
__device__ float g_gsum[NG*D];
__device__ float g_gcnt[NG];
__device__ int g_deg[NN];
__device__ int g_rowstart[NN+1];
__device__ int g_cursor[NN];
__device__ int g_eidx[NE];

__device__ __forceinline__ void bnprep(float* al, float* bes, int slot, float invn,
                                       const float* __restrict__ g,
                                       const float* __restrict__ bb, int t) {
    if (t < 64) {
        float m = g_sum[slot*64+t] * invn;
        float v = fmaxf(g_sq[slot*64+t] * invn - m*m, 0.f);
        float a = g[t] * rsqrtf(v + EPSB);
        al[t] = a; bes[t] = bb[t] - a*m;
    }
}

__device__ __forceinline__ uint32_t smem_u32(const void* p) {
    uint32_t a;
    asm("{ .reg .u64 t; cvta.to.shared.u64 t, %1; cvt.u32.u64 %0, t; }" : "=r"(a) : "l"(p));
    return a;
}
#define SW128(x) ((x) ^ (((x) >> 3) & 0x70))

__device__ __forceinline__ void ldsm4(unsigned* r, uint32_t addr) {
    asm volatile("ldmatrix.sync.aligned.m8n8.x4.shared.b16 {%0,%1,%2,%3}, [%4];"
        : "=r"(r[0]), "=r"(r[1]), "=r"(r[2]), "=r"(r[3]) : "r"(addr));
}
__device__ __forceinline__ void mma16816(float* c, const unsigned* a, const unsigned* b) {
    asm volatile("mma.sync.aligned.m16n8k16.row.col.f32.bf16.bf16.f32 "
        "{%0,%1,%2,%3}, {%4,%5,%6,%7}, {%8,%9}, {%0,%1,%2,%3};"
        : "+f"(c[0]), "+f"(c[1]), "+f"(c[2]), "+f"(c[3])
        : "r"(a[0]), "r"(a[1]), "r"(a[2]), "r"(a[3]), "r"(b[0]), "r"(b[1]));
}

__device__ __forceinline__ void mma_tile(uint32_t abase, uint32_t bbase, int w, int lane,
                                         float c[2][8][4]) {
    int g = lane >> 3;
    int arow = w*32 + ((g & 1) << 3) + (lane & 7);
    int ax7 = arow & 7, bx7 = lane & 7;
#pragma unroll
    for (int ks = 0; ks < 4; ks++) {
        unsigned a0[4], a1[4];
        uint32_t ad = abase + arow*128 + (((ks*2 + (g >> 1)) ^ ax7) << 4);
        ldsm4(a0, ad);
        ldsm4(a1, ad + 16*128);
        unsigned bfr[8][2];
#pragma unroll
        for (int p = 0; p < 4; p++) {
            int nrow = ((2*p + (g >> 1)) << 3) + (lane & 7);
            uint32_t bd = bbase + nrow*128 + (((ks*2 + (g & 1)) ^ bx7) << 4);
            unsigned r[4];
            ldsm4(r, bd);
            bfr[2*p][0] = r[0]; bfr[2*p][1] = r[1];
            bfr[2*p+1][0] = r[2]; bfr[2*p+1][1] = r[3];
        }
#pragma unroll
        for (int nj = 0; nj < 8; nj++) {
            mma16816(c[0][nj], a0, bfr[nj]);
            mma16816(c[1][nj], a1, bfr[nj]);
        }
    }
}

__device__ __forceinline__ void build_A_f32(char* smc, int offA, const float* __restrict__ src,
                                            int t, bool valid) {
#pragma unroll
    for (int q = 0; q < 8; q++) {
        uint4 o = {0u, 0u, 0u, 0u};
        if (valid) {
            float4 v0 = *(const float4*)(src + q*8);
            float4 v1 = *(const float4*)(src + q*8 + 4);
            __nv_bfloat162 p0 = __floats2bfloat162_rn(v0.x, v0.y);
            __nv_bfloat162 p1 = __floats2bfloat162_rn(v0.z, v0.w);
            __nv_bfloat162 p2 = __floats2bfloat162_rn(v1.x, v1.y);
            __nv_bfloat162 p3 = __floats2bfloat162_rn(v1.z, v1.w);
            o.x = *(unsigned*)&p0; o.y = *(unsigned*)&p1;
            o.z = *(unsigned*)&p2; o.w = *(unsigned*)&p3;
        }
        *(uint4*)(smc + offA + SW128(t*128 + q*16)) = o;
    }
}

__device__ __forceinline__ void build_B_W(char* smc, int offB, const float* __restrict__ Wbase, int n) {
#pragma unroll
    for (int kq = 0; kq < 8; kq++) {
        unsigned p[4];
#pragma unroll
        for (int jp = 0; jp < 4; jp++) {
            float w0 = Wbase[(kq*8 + jp*2    )*64 + n];
            float w1 = Wbase[(kq*8 + jp*2 + 1)*64 + n];
            __nv_bfloat162 h = __floats2bfloat162_rn(w0, w1);
            p[jp] = *(unsigned*)&h;
        }
        uint4 o = {p[0], p[1], p[2], p[3]};
        *(uint4*)(smc + offB + SW128(n*128 + kq*16)) = o;
    }
}

__device__ __forceinline__ void store_f32(float* __restrict__ out, const float* bias,
                                          int base, int w, int lane, float c[2][8][4]) {
    int r = lane >> 2, cc = (lane & 3)*2;
#pragma unroll
    for (int nj = 0; nj < 8; nj++) {
        int col = nj*8 + cc;
        float b0 = bias ? bias[col] : 0.f, b1 = bias ? bias[col+1] : 0.f;
#pragma unroll
        for (int mi = 0; mi < 2; mi++) {
            int row = base + w*32 + mi*16 + r;
            if (row < NN) {
                float2 o = {c[mi][nj][0]+b0, c[mi][nj][1]+b1};
                *(float2*)(out + (size_t)row*64 + col) = o;
            }
            if (row + 8 < NN) {
                float2 o = {c[mi][nj][2]+b0, c[mi][nj][3]+b1};
                *(float2*)(out + (size_t)(row+8)*64 + col) = o;
            }
        }
    }
}

__device__ __forceinline__ void store_f32_stats(float* __restrict__ out, const float* bias,
                                                int base, int w, int lane, float c[2][8][4],
                                                float* ssum, float* ssq) {
    int r = lane >> 2, cc = (lane & 3)*2;
#pragma unroll
    for (int nj = 0; nj < 8; nj++) {
        int col = nj*8 + cc;
        float b0 = bias[col], b1 = bias[col+1];
        float s0 = 0.f, s1 = 0.f, q0 = 0.f, q1 = 0.f;
#pragma unroll
        for (int mi = 0; mi < 2; mi++) {
            int row = base + w*32 + mi*16 + r;
            float v00 = c[mi][nj][0]+b0, v01 = c[mi][nj][1]+b1;
            float v10 = c[mi][nj][2]+b0, v11 = c[mi][nj][3]+b1;
            if (row < NN) {
                s0 += v00; s1 += v01; q0 += v00*v00; q1 += v01*v01;
                float2 o = {v00, v01};
                *(float2*)(out + (size_t)row*64 + col) = o;
            }
            if (row + 8 < NN) {
                s0 += v10; s1 += v11; q0 += v10*v10; q1 += v11*v11;
                float2 o = {v10, v11};
                *(float2*)(out + (size_t)(row+8)*64 + col) = o;
            }
        }
#pragma unroll
        for (int off = 16; off >= 4; off >>= 1) {
            s0 += __shfl_down_sync(~0u, s0, off);
            s1 += __shfl_down_sync(~0u, s1, off);
            q0 += __shfl_down_sync(~0u, q0, off);
            q1 += __shfl_down_sync(~0u, q1, off);
        }
        if (lane < 4) {
            atomicAdd(&ssum[col], s0); atomicAdd(&ssum[col+1], s1);
            atomicAdd(&ssq[col],  q0); atomicAdd(&ssq[col+1],  q1);
        }
    }
}

#define NK_A   1024
#define NK_B   17408
#define NK_RED 25600
#define SM_NK  26112

// ---------- input projection + fused zeroing ----------
__global__ void k_lin_in(const float* __restrict__ x, const float* __restrict__ W,
                         const float* __restrict__ b) {
    __shared__ float Ws[IND*D];
    __shared__ float bs[D];
    int gi = blockIdx.x*256 + threadIdx.x;
    if (gi < NN) { g_deg[gi] = 0; g_cursor[gi] = 0; }
    if (gi < 1024) { g_sum[gi] = 0.f; g_sq[gi] = 0.f; }
    if (gi < NG*D) g_gsum[gi] = 0.f;
    if (gi < NG)   g_gcnt[gi] = 0.f;
    for (int i = threadIdx.x; i < IND*D; i += 256) Ws[i] = W[i];
    if (threadIdx.x < D) bs[threadIdx.x] = b[threadIdx.x];
    __syncthreads();
    int node = gi >> 2, c0 = (gi & 3) * 16;
    if (node >= NN) return;
    float xs[IND];
#pragma unroll
    for (int k = 0; k < IND; k++) xs[k] = x[node*IND + k];
#pragma unroll
    for (int j = 0; j < 16; j++) {
        int c = c0 + j;
        float acc = bs[c];
#pragma unroll
        for (int k = 0; k < IND; k++) acc = fmaf(xs[k], Ws[k*D + c], acc);
        g_h[node*D + c] = acc;
    }
}

// ---------- CSR build ----------
__global__ void k_hist(const int* __restrict__ dst) {
    int e = blockIdx.x*256 + threadIdx.x;
    if (e < NE) atomicAdd(&g_deg[dst[e]], 1);
}

__global__ void k_scan() {
    __shared__ int wsum[32];
    __shared__ int carry;
    int t = threadIdx.x, lane = t & 31, w = t >> 5;
    if (t == 0) carry = 0;
    __syncthreads();
    for (int base = 0; base < NN; base += 1024) {
        int i = base + t;
        int v = (i < NN) ? g_deg[i] : 0;
        int x = v;
        for (int o = 1; o < 32; o <<= 1) { int y = __shfl_up_sync(~0u, x, o); if (lane >= o) x += y; }
        if (lane == 31) wsum[w] = x;
        __syncthreads();
        if (w == 0) {
            int s = wsum[lane];
            for (int o = 1; o < 32; o <<= 1) { int y = __shfl_up_sync(~0u, s, o); if (lane >= o) s += y; }
            wsum[lane] = s;
        }
        __syncthreads();
        int excl = carry + x - v + ((w > 0) ? wsum[w-1] : 0);
        if (i < NN) g_rowstart[i] = excl;
        __syncthreads();
        if (t == 0) carry += wsum[31];
        __syncthreads();
    }
    if (threadIdx.x == 0) g_rowstart[NN] = carry;
}

__global__ void k_scatter(const int* __restrict__ dst) {
    int e = blockIdx.x*256 + threadIdx.x;
    if (e < NE) {
        int d = dst[e];
        g_eidx[g_rowstart[d] + atomicAdd(&g_cursor[d], 1)] = e;
    }
}

// ---------- nodePQ (mma) ----------
__global__ void __launch_bounds__(128) k_nodePQ(const float* __restrict__ W1,
                                                const float* __restrict__ b1) {
    extern __shared__ char smc[];
    uint32_t sb = smem_u32(smc);
    float* b1s = (float*)(smc + 16);
    int t = threadIdx.x, w = t >> 5, lane = t & 31;
    int base = blockIdx.x*128, n = base + t;
    if (t < 64) b1s[t] = b1[t];
    build_A_f32(smc, NK_A, g_h + (size_t)n*64, t, n < NN);
    if (t < 64) build_B_W(smc, NK_B, W1, t);
    __syncthreads();
    float c[2][8][4];
#pragma unroll
    for (int i = 0; i < 2; i++)
#pragma unroll
        for (int j = 0; j < 8; j++)
#pragma unroll
            for (int v = 0; v < 4; v++) c[i][j][v] = 0.f;
    mma_tile(sb + NK_A, sb + NK_B, w, lane, c);
    store_f32(g_P, b1s, base, w, lane, c);
    __syncthreads();
    if (t < 64) build_B_W(smc, NK_B, W1 + 4096, t);
    __syncthreads();
#pragma unroll
    for (int i = 0; i < 2; i++)
#pragma unroll
        for (int j = 0; j < 8; j++)
#pragma unroll
            for (int v = 0; v < 4; v++) c[i][j][v] = 0.f;
    mma_tile(sb + NK_A, sb + NK_B, w, lane, c);
    store_f32(g_Q, (const float*)0, base, w, lane, c);
}

// ---------- fused residual(l) + nodePQ(l+1) ----------
__global__ void __launch_bounds__(128) k_residPQ(const float* __restrict__ g4, const float* __restrict__ be4,
                                                 int slot4,
                                                 const float* __restrict__ W1, const float* __restrict__ b1) {
    extern __shared__ char smc[];
    uint32_t sb = smem_u32(smc);
    float* al  = (float*)(smc + 16);
    float* be  = (float*)(smc + 16 + 256);
    float* b1s = (float*)(smc + 16 + 512);
    int t = threadIdx.x, w = t >> 5, lane = t & 31;
    int base = blockIdx.x*128, n = base + t;
    bnprep(al, be, slot4, 1.f/NN, g4, be4, t);
    if (t < 64) b1s[t] = b1[t];
    __syncthreads();
    if (n < NN) {
        float4* hp = (float4*)(g_h + (size_t)n*64);
        const float4* yp = (const float4*)(g_y4 + (size_t)n*64);
#pragma unroll
        for (int q = 0; q < 8; q++) {
            float4 h0 = hp[2*q], h1 = hp[2*q+1];
            float4 v0 = yp[2*q], v1 = yp[2*q+1];
            int c = q*8;
            h0.x += fmaxf(fmaf(al[c+0], v0.x, be[c+0]), 0.f);
            h0.y += fmaxf(fmaf(al[c+1], v0.y, be[c+1]), 0.f);
            h0.z += fmaxf(fmaf(al[c+2], v0.z, be[c+2]), 0.f);
            h0.w += fmaxf(fmaf(al[c+3], v0.w, be[c+3]), 0.f);
            h1.x += fmaxf(fmaf(al[c+4], v1.x, be[c+4]), 0.f);
            h1.y += fmaxf(fmaf(al[c+5], v1.y, be[c+5]), 0.f);
            h1.z += fmaxf(fmaf(al[c+6], v1.z, be[c+6]), 0.f);
            h1.w += fmaxf(fmaf(al[c+7], v1.w, be[c+7]), 0.f);
            hp[2*q] = h0; hp[2*q+1] = h1;
            __nv_bfloat162 p0 = __floats2bfloat162_rn(h0.x, h0.y);
            __nv_bfloat162 p1 = __floats2bfloat162_rn(h0.z, h0.w);
            __nv_bfloat162 p2 = __floats2bfloat162_rn(h1.x, h1.y);
            __nv_bfloat162 p3 = __floats2bfloat162_rn(h1.z, h1.w);
            uint4 o = { *(unsigned*)&p0, *(unsigned*)&p1, *(unsigned*)&p2, *(unsigned*)&p3 };
            *(uint4*)(smc + NK_A + SW128(t*128 + q*16)) = o;
        }
    } else {
        uint4 z = {0u,0u,0u,0u};
#pragma unroll
        for (int q = 0; q < 8; q++)
            *(uint4*)(smc + NK_A + SW128(t*128 + q*16)) = z;
    }
    if (t < 64) build_B_W(smc, NK_B, W1, t);
    __syncthreads();
    float c[2][8][4];
#pragma unroll
    for (int i = 0; i < 2; i++)
#pragma unroll
        for (int j = 0; j < 8; j++)
#pragma unroll
            for (int v = 0; v < 4; v++) c[i][j][v] = 0.f;
    mma_tile(sb + NK_A, sb + NK_B, w, lane, c);
    store_f32(g_P, b1s, base, w, lane, c);
    __syncthreads();
    if (t < 64) build_B_W(smc, NK_B, W1 + 4096, t);
    __syncthreads();
#pragma unroll
    for (int i = 0; i < 2; i++)
#pragma unroll
        for (int j = 0; j < 8; j++)
#pragma unroll
            for (int v = 0; v < 4; v++) c[i][j][v] = 0.f;
    mma_tile(sb + NK_A, sb + NK_B, w, lane, c);
    store_f32(g_Q, (const float*)0, base, w, lane, c);
}

// ---------- pass A: CSR-ordered, fp32 P/Q ----------
__global__ void __launch_bounds__(256) k_edgeA(const int* __restrict__ src, const int* __restrict__ dst,
                                               const float* __restrict__ ea, const float* __restrict__ W1, int slot) {
    __shared__ float Weas[256];
    __shared__ float ssum[64], ssq[64];
    int t = threadIdx.x;
    for (int i = t; i < 256; i += 256) Weas[i] = W1[8192 + i];
    if (t < 64) { ssum[t] = 0.f; ssq[t] = 0.f; }
    __syncthreads();
    int wg = (blockIdx.x*256 + t) >> 5, lane = t & 31;
    int nw = gridDim.x*8;
    int half = lane >> 4, c4 = (lane & 15) * 4;
    u64 wA0 = *(const u64*)(Weas + c4),       wB0 = *(const u64*)(Weas + c4 + 2);
    u64 wA1 = *(const u64*)(Weas + 64 + c4),  wB1 = *(const u64*)(Weas + 64 + c4 + 2);
    u64 wA2 = *(const u64*)(Weas + 128 + c4), wB2 = *(const u64*)(Weas + 128 + c4 + 2);
    u64 wA3 = *(const u64*)(Weas + 192 + c4), wB3 = *(const u64*)(Weas + 192 + c4 + 2);
    u64 spA = 0ull, spB = 0ull, qpA = 0ull, qpB = 0ull;
    for (int ib = wg*2; ib < NE; ib += nw*2) {
        int i = ib + half;
        if (i < NE) {
            int e = g_eidx[i];
            int s = src[e], d = dst[e];
            float4 ev = *(const float4*)(ea + (size_t)e*4);
            ulonglong2 Pv = *(const ulonglong2*)(g_P + (size_t)d*64 + c4);
            ulonglong2 Qv = *(const ulonglong2*)(g_Q + (size_t)s*64 + c4);
            u64 e0, e1, e2, e3;
            F2BCAST(e0, ev.x); F2BCAST(e1, ev.y); F2BCAST(e2, ev.z); F2BCAST(e3, ev.w);
            u64 yA; F2ADD(yA, Pv.x, Qv.x);
            F2FMA(yA, e0, wA0); F2FMA(yA, e1, wA1); F2FMA(yA, e2, wA2); F2FMA(yA, e3, wA3);
            u64 yB; F2ADD(yB, Pv.y, Qv.y);
            F2FMA(yB, e0, wB0); F2FMA(yB, e1, wB1); F2FMA(yB, e2, wB2); F2FMA(yB, e3, wB3);
            F2ADD(spA, spA, yA); F2FMA(qpA, yA, yA);
            F2ADD(spB, spB, yB); F2FMA(qpB, yB, yB);
            float a0, a1, b0, b1;
            F2UNPACK(a0, a1, yA); F2UNPACK(b0, b1, yB);
            __nv_bfloat162 h0 = __floats2bfloat162_rn(a0, a1);
            __nv_bfloat162 h1 = __floats2bfloat162_rn(b0, b1);
            uint2 o = { *(unsigned*)&h0, *(unsigned*)&h1 };
            *(uint2*)(g_y1 + (size_t)i*64 + c4) = o;
        }
    }
    float v0, v1, v2, v3, q0, q1, q2, q3;
    F2UNPACK(v0, v1, spA); F2UNPACK(v2, v3, spB);
    F2UNPACK(q0, q1, qpA); F2UNPACK(q2, q3, qpB);
    atomicAdd(&ssum[c4+0], v0); atomicAdd(&ssum[c4+1], v1);
    atomicAdd(&ssum[c4+2], v2); atomicAdd(&ssum[c4+3], v3);
    atomicAdd(&ssq[c4+0], q0); atomicAdd(&ssq[c4+1], q1);
    atomicAdd(&ssq[c4+2], q2); atomicAdd(&ssq[c4+3], q3);
    __syncthreads();
    if (t < 64) { atomicAdd(&g_sum[slot*64+t], ssum[t]); atomicAdd(&g_sq[slot*64+t], ssq[t]); }
}

// ---------- pass B: mma 128x64x64, register epilogue ----------
__global__ void __launch_bounds__(128) k_edgeB(const float* __restrict__ W2, const float* __restrict__ b2,
                                               const float* __restrict__ g1, const float* __restrict__ be1,
                                               int slot_in, int slot_out) {
    extern __shared__ char smc[];
    uint32_t sb = smem_u32(smc);
    float* al  = (float*)(smc + 16);
    float* be  = (float*)(smc + 16 + 256);
    float* b2s = (float*)(smc + 16 + 512);
    float* ssum = (float*)(smc + NK_RED);
    float* ssq  = ssum + 64;
    int t = threadIdx.x, w = t >> 5, lane = t & 31;
    int base = blockIdx.x * 128;
    bnprep(al, be, slot_in, 1.f/NE, g1, be1, t);
    if (t < 64) { b2s[t] = b2[t]; ssum[t] = 0.f; ssq[t] = 0.f; }
    __syncthreads();
    {
        const uint4* yp = (const uint4*)(g_y1 + (size_t)(base + t)*64);
#pragma unroll
        for (int q = 0; q < 8; q++) {
            uint4 u = yp[q];
            int c = q*8;
            float2 f0 = __bfloat1622float2(*(__nv_bfloat162*)&u.x);
            float2 f1 = __bfloat1622float2(*(__nv_bfloat162*)&u.y);
            float2 f2 = __bfloat1622float2(*(__nv_bfloat162*)&u.z);
            float2 f3 = __bfloat1622float2(*(__nv_bfloat162*)&u.w);
            float y0 = fmaxf(fmaf(al[c+0], f0.x, be[c+0]), 0.f);
            float y1v= fmaxf(fmaf(al[c+1], f0.y, be[c+1]), 0.f);
            float y2v= fmaxf(fmaf(al[c+2], f1.x, be[c+2]), 0.f);
            float y3v= fmaxf(fmaf(al[c+3], f1.y, be[c+3]), 0.f);
            float y4v= fmaxf(fmaf(al[c+4], f2.x, be[c+4]), 0.f);
            float y5 = fmaxf(fmaf(al[c+5], f2.y, be[c+5]), 0.f);
            float y6 = fmaxf(fmaf(al[c+6], f3.x, be[c+6]), 0.f);
            float y7 = fmaxf(fmaf(al[c+7], f3.y, be[c+7]), 0.f);
            __nv_bfloat162 p0 = __floats2bfloat162_rn(y0, y1v);
            __nv_bfloat162 p1 = __floats2bfloat162_rn(y2v, y3v);
            __nv_bfloat162 p2 = __floats2bfloat162_rn(y4v, y5);
            __nv_bfloat162 p3 = __floats2bfloat162_rn(y6, y7);
            uint4 o = { *(unsigned*)&p0, *(unsigned*)&p1, *(unsigned*)&p2, *(unsigned*)&p3 };
            *(uint4*)(smc + NK_A + SW128(t*128 + q*16)) = o;
        }
    }
    if (t < 64) build_B_W(smc, NK_B, W2, t);
    __syncthreads();
    float c[2][8][4];
#pragma unroll
    for (int i = 0; i < 2; i++)
#pragma unroll
        for (int j = 0; j < 8; j++)
#pragma unroll
            for (int v = 0; v < 4; v++) c[i][j][v] = 0.f;
    mma_tile(sb + NK_A, sb + NK_B, w, lane, c);
    int r = lane >> 2, cc = (lane & 3)*2;
#pragma unroll
    for (int nj = 0; nj < 8; nj++) {
        int col = nj*8 + cc;
        float b0 = b2s[col], b1 = b2s[col+1];
        float s0 = 0.f, s1 = 0.f, q0 = 0.f, q1 = 0.f;
#pragma unroll
        for (int mi = 0; mi < 2; mi++) {
            float v00 = c[mi][nj][0] + b0, v01 = c[mi][nj][1] + b1;
            float v10 = c[mi][nj][2] + b0, v11 = c[mi][nj][3] + b1;
            s0 += v00 + v10; s1 += v01 + v11;
            q0 += v00*v00 + v10*v10; q1 += v01*v01 + v11*v11;
            size_t row0 = (size_t)(base + w*32 + mi*16 + r);
            __nv_bfloat162 h0 = __floats2bfloat162_rn(v00, v01);
            __nv_bfloat162 h1 = __floats2bfloat162_rn(v10, v11);
            *(unsigned*)(g_y2 + row0*64 + col)       = *(unsigned*)&h0;
            *(unsigned*)(g_y2 + (row0 + 8)*64 + col) = *(unsigned*)&h1;
        }
#pragma unroll
        for (int off = 16; off >= 4; off >>= 1) {
            s0 += __shfl_down_sync(~0u, s0, off);
            s1 += __shfl_down_sync(~0u, s1, off);
            q0 += __shfl_down_sync(~0u, q0, off);
            q1 += __shfl_down_sync(~0u, q1, off);
        }
        if (lane < 4) {
            atomicAdd(&ssum[col], s0); atomicAdd(&ssum[col+1], s1);
            atomicAdd(&ssq[col],  q0); atomicAdd(&ssq[col+1],  q1);
        }
    }
    __syncthreads();
    if (t < 64) {
        atomicAdd(&g_sum[slot_out*64 + t], ssum[t]);
        atomicAdd(&g_sq [slot_out*64 + t], ssq[t]);
    }
}

// ---------- nodeU1 (mma, K=128) with FUSED aggregation ----------
__global__ void __launch_bounds__(128) k_nodeU1(const float* __restrict__ W,
                                                const float* __restrict__ b3,
                                                const float* __restrict__ g2, const float* __restrict__ be2,
                                                int slot2, int slot_out) {
    extern __shared__ char smc[];
    uint32_t sb = smem_u32(smc);
    float* al2 = (float*)(smc + 16);
    float* be2s= (float*)(smc + 16 + 256);
    float* b3s = (float*)(smc + 16 + 512);
    float* ssum = (float*)(smc + NK_RED);
    float* ssq  = ssum + 64;
    int t = threadIdx.x, w = t >> 5, lane = t & 31;
    int base = blockIdx.x*128, n = base + t;
    bnprep(al2, be2s, slot2, 1.f/NE, g2, be2, t);
    if (t < 64) { b3s[t] = b3[t]; ssum[t] = 0.f; ssq[t] = 0.f; }
    build_A_f32(smc, NK_A, g_h + (size_t)n*64, t, n < NN);
    if (t < 64) build_B_W(smc, NK_B, W, t);
    __syncthreads();
    float c[2][8][4];
#pragma unroll
    for (int i = 0; i < 2; i++)
#pragma unroll
        for (int j = 0; j < 8; j++)
#pragma unroll
            for (int v = 0; v < 4; v++) c[i][j][v] = 0.f;
    mma_tile(sb + NK_A, sb + NK_B, w, lane, c);
    __syncthreads();
    // fused aggregation into A tile (bf16): warp w handles rows [w*32, w*32+32)
    {
        float alA = al2[2*lane], beA = be2s[2*lane];
        float alB = al2[2*lane+1], beB = be2s[2*lane+1];
        const __nv_bfloat162* y = (const __nv_bfloat162*)g_y2;
        for (int i = 0; i < 32; i++) {
            int row = w*32 + i;
            int nn = base + row;
            float a0 = 0.f, a1 = 0.f;
            if (nn < NN) {
                int s = g_rowstart[nn], e = g_rowstart[nn+1];
                for (int p = s; p < e; p++) {
                    float2 v = __bfloat1622float2(y[(size_t)p*32 + lane]);
                    a0 += fmaxf(fmaf(alA, v.x, beA), 0.f);
                    a1 += fmaxf(fmaf(alB, v.y, beB), 0.f);
                }
            }
            __nv_bfloat162 h = __floats2bfloat162_rn(a0, a1);
            *(unsigned*)(smc + NK_A + SW128(row*128 + lane*4)) = *(unsigned*)&h;
        }
    }
    if (t < 64) build_B_W(smc, NK_B, W + 4096, t);
    __syncthreads();
    mma_tile(sb + NK_A, sb + NK_B, w, lane, c);
    store_f32_stats(g_y3, b3s, base, w, lane, c, ssum, ssq);
    __syncthreads();
    if (t < 64) {
        atomicAdd(&g_sum[slot_out*64 + t], ssum[t]);
        atomicAdd(&g_sq [slot_out*64 + t], ssq[t]);
    }
}

// ---------- nodeU2 (mma) ----------
__global__ void __launch_bounds__(128) k_nodeU2(const float* __restrict__ W,
                                                const float* __restrict__ b4,
                                                const float* __restrict__ g3, const float* __restrict__ be3,
                                                int slot_in, int slot_out) {
    extern __shared__ char smc[];
    uint32_t sb = smem_u32(smc);
    float* al  = (float*)(smc + 16);
    float* be  = (float*)(smc + 16 + 256);
    float* b4s = (float*)(smc + 16 + 512);
    float* ssum = (float*)(smc + NK_RED);
    float* ssq  = ssum + 64;
    int t = threadIdx.x, w = t >> 5, lane = t & 31;
    int base = blockIdx.x*128, n = base + t;
    bnprep(al, be, slot_in, 1.f/NN, g3, be3, t);
    if (t < 64) { b4s[t] = b4[t]; ssum[t] = 0.f; ssq[t] = 0.f; }
    __syncthreads();
    if (n < NN) {
        const float4* yp = (const float4*)(g_y3 + (size_t)n*64);
#pragma unroll
        for (int q = 0; q < 8; q++) {
            float4 v0 = yp[2*q], v1 = yp[2*q+1];
            int c = q*8;
            float y0 = fmaxf(fmaf(al[c+0], v0.x, be[c+0]), 0.f);
            float y1v= fmaxf(fmaf(al[c+1], v0.y, be[c+1]), 0.f);
            float y2v= fmaxf(fmaf(al[c+2], v0.z, be[c+2]), 0.f);
            float y3v= fmaxf(fmaf(al[c+3], v0.w, be[c+3]), 0.f);
            float y4v= fmaxf(fmaf(al[c+4], v1.x, be[c+4]), 0.f);
            float y5 = fmaxf(fmaf(al[c+5], v1.y, be[c+5]), 0.f);
            float y6 = fmaxf(fmaf(al[c+6], v1.z, be[c+6]), 0.f);
            float y7 = fmaxf(fmaf(al[c+7], v1.w, be[c+7]), 0.f);
            __nv_bfloat162 p0 = __floats2bfloat162_rn(y0, y1v);
            __nv_bfloat162 p1 = __floats2bfloat162_rn(y2v, y3v);
            __nv_bfloat162 p2 = __floats2bfloat162_rn(y4v, y5);
            __nv_bfloat162 p3 = __floats2bfloat162_rn(y6, y7);
            uint4 o = { *(unsigned*)&p0, *(unsigned*)&p1, *(unsigned*)&p2, *(unsigned*)&p3 };
            *(uint4*)(smc + NK_A + SW128(t*128 + q*16)) = o;
        }
    } else {
        uint4 z = {0u,0u,0u,0u};
#pragma unroll
        for (int q = 0; q < 8; q++)
            *(uint4*)(smc + NK_A + SW128(t*128 + q*16)) = z;
    }
    if (t < 64) build_B_W(smc, NK_B, W, t);
    __syncthreads();
    float c[2][8][4];
#pragma unroll
    for (int i = 0; i < 2; i++)
#pragma unroll
        for (int j = 0; j < 8; j++)
#pragma unroll
            for (int v = 0; v < 4; v++) c[i][j][v] = 0.f;
    mma_tile(sb + NK_A, sb + NK_B, w, lane, c);
    store_f32_stats(g_y4, b4s, base, w, lane, c, ssum, ssq);
    __syncthreads();
    if (t < 64) {
        atomicAdd(&g_sum[slot_out*64 + t], ssum[t]);
        atomicAdd(&g_sq [slot_out*64 + t], ssq[t]);
    }
}

// ---------- residual (last layer only) ----------
__global__ void __launch_bounds__(256) k_resid(const float* __restrict__ g4, const float* __restrict__ be4, int slot) {
    __shared__ float al[64], be[64];
    bnprep(al, be, slot, 1.f/NN, g4, be4, threadIdx.x);
    __syncthreads();
    int i = blockIdx.x*256 + threadIdx.x;
    if (i < NN*D) {
        int c = i & 63;
        g_h[i] += fmaxf(fmaf(al[c], g_y4[i], be[c]), 0.f);
    }
}

// ---------- pooling ----------
__global__ void k_pool(const int* __restrict__ batch) {
    int w = blockIdx.x*8 + (threadIdx.x >> 5);
    int lane = threadIdx.x & 31;
    int n0 = w*64, n1 = min(n0 + 64, NN);
    if (n0 >= NN) return;
    float ax = 0.f, ay = 0.f, cnt = 0.f;
    int curg = batch[n0];
    for (int n = n0; n < n1; n++) {
        int g = batch[n];
        if (g != curg) {
            atomicAdd(&g_gsum[curg*64 + 2*lane], ax);
            atomicAdd(&g_gsum[curg*64 + 2*lane + 1], ay);
            if (lane == 0) atomicAdd(&g_gcnt[curg], cnt);
            ax = 0.f; ay = 0.f; cnt = 0.f; curg = g;
        }
        float2 v = *(const float2*)(g_h + n*64 + 2*lane);
        ax += v.x; ay += v.y; cnt += 1.f;
    }
    atomicAdd(&g_gsum[curg*64 + 2*lane], ax);
    atomicAdd(&g_gsum[curg*64 + 2*lane + 1], ay);
    if (lane == 0) atomicAdd(&g_gcnt[curg], cnt);
}

__global__ void k_pred(const float* __restrict__ pW, const float* __restrict__ pb,
                       float* __restrict__ out) {
    int g = threadIdx.x;
    if (g < NG) {
        float cnt = fmaxf(g_gcnt[g], 1.f);
        float acc = pb[0];
        for (int c = 0; c < D; c++) acc += g_gsum[g*64 + c] / cnt * pW[c];
        out[g] = acc;
    }
}

extern "C" void kernel_launch(void* const* d_in, const int* in_sizes, int n_in,
                              void* d_out, int out_size) {
    const float* x    = (const float*)d_in[0];
    const float* ea   = (const float*)d_in[1];
    const int*   ei   = (const int*)d_in[2];
    const int*   batch= (const int*)d_in[3];
    const float* linW = (const float*)d_in[4];
    const float* linb = (const float*)d_in[5];
    const float* mW1  = (const float*)d_in[6];
    const float* mb1  = (const float*)d_in[7];
    const float* mg1  = (const float*)d_in[8];
    const float* mbe1 = (const float*)d_in[9];
    const float* mW2  = (const float*)d_in[10];
    const float* mb2  = (const float*)d_in[11];
    const float* mg2  = (const float*)d_in[12];
    const float* mbe2 = (const float*)d_in[13];
    const float* uW1  = (const float*)d_in[14];
    const float* ub1  = (const float*)d_in[15];
    const float* ug1  = (const float*)d_in[16];
    const float* ube1 = (const float*)d_in[17];
    const float* uW2  = (const float*)d_in[18];
    const float* ub2  = (const float*)d_in[19];
    const float* ug2  = (const float*)d_in[20];
    const float* ube2 = (const float*)d_in[21];
    const float* pW   = (const float*)d_in[22];
    const float* pb   = (const float*)d_in[23];
    float* out = (float*)d_out;
    const int* src = ei;
    const int* dst = ei + NE;

    int nblk = (NN + 127) / 128;

    k_lin_in<<<(NN*4+255)/256, 256>>>(x, linW, linb);
    k_hist<<<(NE+255)/256, 256>>>(dst);
    k_scan<<<1, 1024>>>();
    k_nodePQ<<<nblk, 128, SM_NK>>>(mW1, mb1);
    k_scatter<<<(NE+255)/256, 256>>>(dst);

    for (int l = 0; l < 4; l++) {
        const float* W1 = mW1 + l*132*64;
        int s0 = l*4;
        k_edgeA<<<592, 256>>>(src, dst, ea, W1, s0);
        k_edgeB<<<NE/128, 128, SM_NK>>>(mW2 + l*4096, mb2 + l*64,
                                        mg1 + l*64, mbe1 + l*64, s0, s0+1);
        k_nodeU1<<<nblk, 128, SM_NK>>>(uW1 + l*128*64, ub1 + l*64,
                                       mg2 + l*64, mbe2 + l*64, s0+1, s0+2);
        k_nodeU2<<<nblk, 128, SM_NK>>>(uW2 + l*4096, ub2 + l*64,
                                       ug1 + l*64, ube1 + l*64, s0+2, s0+3);
        if (l < 3) {
            k_residPQ<<<nblk, 128, SM_NK>>>(ug2 + l*64, ube2 + l*64, s0+3,
                                            mW1 + (l+1)*132*64, mb1 + (l+1)*64);
        } else {
            k_resid<<<(NN*D+255)/256, 256>>>(ug2 + l*64, ube2 + l*64, s0+3);
        }
    }
    k_pool<<<98, 256>>>(batch);
    k_pred<<<1, 32>>>(pW, pb, out);
}

// round 16
// speedup vs baseline: 1.1353x; 1.1353x over previous
#include <cuda_runtime.h>
#include <cuda_bf16.h>
#include <cstdint>

#define NN 50000
#define NE 400000
#define NG 32
#define D  64
#define IND 11
#define EPSB 1e-5f

typedef unsigned long long u64;

#define F2FMA(acc, a, b) asm("fma.rn.f32x2 %0, %1, %2, %0;" : "+l"(acc) : "l"(a), "l"(b))
#define F2ADD(d, a, b)   asm("add.rn.f32x2 %0, %1, %2;" : "=l"(d) : "l"(a), "l"(b))
#define F2BCAST(d, x)    { unsigned _u = __float_as_uint(x); asm("mov.b64 %0, {%1, %1};" : "=l"(d) : "r"(_u)); }
#define F2UNPACK(lo, hi, p) { unsigned _a, _b; asm("mov.b64 {%0, %1}, %2;" : "=r"(_a), "=r"(_b) : "l"(p)); lo = __uint_as_float(_a); hi = __uint_as_float(_b); }

__device__ float g_h[NN*D];
__device__ float g_P[NN*D];
__device__ float g_Q[NN*D];
__device__ __nv_bfloat16 g_y1[NE*D];
__device__ __nv_bfloat16 g_y2[NE*D];
__device__ float g_aggr[NN*D];
__device__ float g_y3[NN*D];
__device__ float g_y4[NN*D];
__device__ float g_sum[16*64];
__device__ float g_sq[16*64];
__device__ float g_gsum[NG*D];
__device__ float g_gcnt[NG];
__device__ int g_deg[NN];
__device__ int g_rowstart[NN+1];
__device__ int g_cursor[NN];
__device__ int g_eidx[NE];

__device__ __forceinline__ void bnprep(float* al, float* bes, int slot, float invn,
                                       const float* __restrict__ g,
                                       const float* __restrict__ bb, int t) {
    if (t < 64) {
        float m = g_sum[slot*64+t] * invn;
        float v = fmaxf(g_sq[slot*64+t] * invn - m*m, 0.f);
        float a = g[t] * rsqrtf(v + EPSB);
        al[t] = a; bes[t] = bb[t] - a*m;
    }
}

__device__ __forceinline__ uint32_t smem_u32(const void* p) {
    uint32_t a;
    asm("{ .reg .u64 t; cvta.to.shared.u64 t, %1; cvt.u32.u64 %0, t; }" : "=r"(a) : "l"(p));
    return a;
}
#define SW128(x) ((x) ^ (((x) >> 3) & 0x70))

__device__ __forceinline__ void ldsm4(unsigned* r, uint32_t addr) {
    asm volatile("ldmatrix.sync.aligned.m8n8.x4.shared.b16 {%0,%1,%2,%3}, [%4];"
        : "=r"(r[0]), "=r"(r[1]), "=r"(r[2]), "=r"(r[3]) : "r"(addr));
}
__device__ __forceinline__ void mma16816(float* c, const unsigned* a, const unsigned* b) {
    asm volatile("mma.sync.aligned.m16n8k16.row.col.f32.bf16.bf16.f32 "
        "{%0,%1,%2,%3}, {%4,%5,%6,%7}, {%8,%9}, {%0,%1,%2,%3};"
        : "+f"(c[0]), "+f"(c[1]), "+f"(c[2]), "+f"(c[3])
        : "r"(a[0]), "r"(a[1]), "r"(a[2]), "r"(a[3]), "r"(b[0]), "r"(b[1]));
}

__device__ __forceinline__ void mma_tile(uint32_t abase, uint32_t bbase, int w, int lane,
                                         float c[2][8][4]) {
    int g = lane >> 3;
    int arow = w*32 + ((g & 1) << 3) + (lane & 7);
    int ax7 = arow & 7, bx7 = lane & 7;
#pragma unroll
    for (int ks = 0; ks < 4; ks++) {
        unsigned a0[4], a1[4];
        uint32_t ad = abase + arow*128 + (((ks*2 + (g >> 1)) ^ ax7) << 4);
        ldsm4(a0, ad);
        ldsm4(a1, ad + 16*128);
        unsigned bfr[8][2];
#pragma unroll
        for (int p = 0; p < 4; p++) {
            int nrow = ((2*p + (g >> 1)) << 3) + (lane & 7);
            uint32_t bd = bbase + nrow*128 + (((ks*2 + (g & 1)) ^ bx7) << 4);
            unsigned r[4];
            ldsm4(r, bd);
            bfr[2*p][0] = r[0]; bfr[2*p][1] = r[1];
            bfr[2*p+1][0] = r[2]; bfr[2*p+1][1] = r[3];
        }
#pragma unroll
        for (int nj = 0; nj < 8; nj++) {
            mma16816(c[0][nj], a0, bfr[nj]);
            mma16816(c[1][nj], a1, bfr[nj]);
        }
    }
}

__device__ __forceinline__ void build_A_f32(char* smc, int offA, const float* __restrict__ src,
                                            int t, bool valid) {
#pragma unroll
    for (int q = 0; q < 8; q++) {
        uint4 o = {0u, 0u, 0u, 0u};
        if (valid) {
            float4 v0 = *(const float4*)(src + q*8);
            float4 v1 = *(const float4*)(src + q*8 + 4);
            __nv_bfloat162 p0 = __floats2bfloat162_rn(v0.x, v0.y);
            __nv_bfloat162 p1 = __floats2bfloat162_rn(v0.z, v0.w);
            __nv_bfloat162 p2 = __floats2bfloat162_rn(v1.x, v1.y);
            __nv_bfloat162 p3 = __floats2bfloat162_rn(v1.z, v1.w);
            o.x = *(unsigned*)&p0; o.y = *(unsigned*)&p1;
            o.z = *(unsigned*)&p2; o.w = *(unsigned*)&p3;
        }
        *(uint4*)(smc + offA + SW128(t*128 + q*16)) = o;
    }
}

__device__ __forceinline__ void build_B_W(char* smc, int offB, const float* __restrict__ Wbase, int n) {
#pragma unroll
    for (int kq = 0; kq < 8; kq++) {
        unsigned p[4];
#pragma unroll
        for (int jp = 0; jp < 4; jp++) {
            float w0 = Wbase[(kq*8 + jp*2    )*64 + n];
            float w1 = Wbase[(kq*8 + jp*2 + 1)*64 + n];
            __nv_bfloat162 h = __floats2bfloat162_rn(w0, w1);
            p[jp] = *(unsigned*)&h;
        }
        uint4 o = {p[0], p[1], p[2], p[3]};
        *(uint4*)(smc + offB + SW128(n*128 + kq*16)) = o;
    }
}

__device__ __forceinline__ void store_f32(float* __restrict__ out, const float* bias,
                                          int base, int w, int lane, float c[2][8][4]) {
    int r = lane >> 2, cc = (lane & 3)*2;
#pragma unroll
    for (int nj = 0; nj < 8; nj++) {
        int col = nj*8 + cc;
        float b0 = bias ? bias[col] : 0.f, b1 = bias ? bias[col+1] : 0.f;
#pragma unroll
        for (int mi = 0; mi < 2; mi++) {
            int row = base + w*32 + mi*16 + r;
            if (row < NN) {
                float2 o = {c[mi][nj][0]+b0, c[mi][nj][1]+b1};
                *(float2*)(out + (size_t)row*64 + col) = o;
            }
            if (row + 8 < NN) {
                float2 o = {c[mi][nj][2]+b0, c[mi][nj][3]+b1};
                *(float2*)(out + (size_t)(row+8)*64 + col) = o;
            }
        }
    }
}

__device__ __forceinline__ void store_f32_stats(float* __restrict__ out, const float* bias,
                                                int base, int w, int lane, float c[2][8][4],
                                                float* ssum, float* ssq) {
    int r = lane >> 2, cc = (lane & 3)*2;
#pragma unroll
    for (int nj = 0; nj < 8; nj++) {
        int col = nj*8 + cc;
        float b0 = bias[col], b1 = bias[col+1];
        float s0 = 0.f, s1 = 0.f, q0 = 0.f, q1 = 0.f;
#pragma unroll
        for (int mi = 0; mi < 2; mi++) {
            int row = base + w*32 + mi*16 + r;
            float v00 = c[mi][nj][0]+b0, v01 = c[mi][nj][1]+b1;
            float v10 = c[mi][nj][2]+b0, v11 = c[mi][nj][3]+b1;
            if (row < NN) {
                s0 += v00; s1 += v01; q0 += v00*v00; q1 += v01*v01;
                float2 o = {v00, v01};
                *(float2*)(out + (size_t)row*64 + col) = o;
            }
            if (row + 8 < NN) {
                s0 += v10; s1 += v11; q0 += v10*v10; q1 += v11*v11;
                float2 o = {v10, v11};
                *(float2*)(out + (size_t)(row+8)*64 + col) = o;
            }
        }
#pragma unroll
        for (int off = 16; off >= 4; off >>= 1) {
            s0 += __shfl_down_sync(~0u, s0, off);
            s1 += __shfl_down_sync(~0u, s1, off);
            q0 += __shfl_down_sync(~0u, q0, off);
            q1 += __shfl_down_sync(~0u, q1, off);
        }
        if (lane < 4) {
            atomicAdd(&ssum[col], s0); atomicAdd(&ssum[col+1], s1);
            atomicAdd(&ssq[col],  q0); atomicAdd(&ssq[col+1],  q1);
        }
    }
}

#define NK_A   1024
#define NK_B   17408
#define NK_RED 25600
#define SM_NK  26112

// ---------- input projection + fused zeroing ----------
__global__ void k_lin_in(const float* __restrict__ x, const float* __restrict__ W,
                         const float* __restrict__ b) {
    __shared__ float Ws[IND*D];
    __shared__ float bs[D];
    int gi = blockIdx.x*256 + threadIdx.x;
    if (gi < NN) { g_deg[gi] = 0; g_cursor[gi] = 0; }
    if (gi < 1024) { g_sum[gi] = 0.f; g_sq[gi] = 0.f; }
    if (gi < NG*D) g_gsum[gi] = 0.f;
    if (gi < NG)   g_gcnt[gi] = 0.f;
    for (int i = threadIdx.x; i < IND*D; i += 256) Ws[i] = W[i];
    if (threadIdx.x < D) bs[threadIdx.x] = b[threadIdx.x];
    __syncthreads();
    int node = gi >> 2, c0 = (gi & 3) * 16;
    if (node >= NN) return;
    float xs[IND];
#pragma unroll
    for (int k = 0; k < IND; k++) xs[k] = x[node*IND + k];
#pragma unroll
    for (int j = 0; j < 16; j++) {
        int c = c0 + j;
        float acc = bs[c];
#pragma unroll
        for (int k = 0; k < IND; k++) acc = fmaf(xs[k], Ws[k*D + c], acc);
        g_h[node*D + c] = acc;
    }
}

// ---------- CSR build ----------
__global__ void k_hist(const int* __restrict__ dst) {
    int e = blockIdx.x*256 + threadIdx.x;
    if (e < NE) atomicAdd(&g_deg[dst[e]], 1);
}

__global__ void k_scan() {
    __shared__ int wsum[32];
    __shared__ int carry;
    int t = threadIdx.x, lane = t & 31, w = t >> 5;
    if (t == 0) carry = 0;
    __syncthreads();
    for (int base = 0; base < NN; base += 1024) {
        int i = base + t;
        int v = (i < NN) ? g_deg[i] : 0;
        int x = v;
        for (int o = 1; o < 32; o <<= 1) { int y = __shfl_up_sync(~0u, x, o); if (lane >= o) x += y; }
        if (lane == 31) wsum[w] = x;
        __syncthreads();
        if (w == 0) {
            int s = wsum[lane];
            for (int o = 1; o < 32; o <<= 1) { int y = __shfl_up_sync(~0u, s, o); if (lane >= o) s += y; }
            wsum[lane] = s;
        }
        __syncthreads();
        int excl = carry + x - v + ((w > 0) ? wsum[w-1] : 0);
        if (i < NN) g_rowstart[i] = excl;
        __syncthreads();
        if (t == 0) carry += wsum[31];
        __syncthreads();
    }
    if (threadIdx.x == 0) g_rowstart[NN] = carry;
}

__global__ void k_scatter(const int* __restrict__ dst) {
    int e = blockIdx.x*256 + threadIdx.x;
    if (e < NE) {
        int d = dst[e];
        g_eidx[g_rowstart[d] + atomicAdd(&g_cursor[d], 1)] = e;
    }
}

// ---------- nodePQ (mma) ----------
__global__ void __launch_bounds__(128) k_nodePQ(const float* __restrict__ W1,
                                                const float* __restrict__ b1) {
    extern __shared__ char smc[];
    uint32_t sb = smem_u32(smc);
    float* b1s = (float*)(smc + 16);
    int t = threadIdx.x, w = t >> 5, lane = t & 31;
    int base = blockIdx.x*128, n = base + t;
    if (t < 64) b1s[t] = b1[t];
    build_A_f32(smc, NK_A, g_h + (size_t)n*64, t, n < NN);
    if (t < 64) build_B_W(smc, NK_B, W1, t);
    __syncthreads();
    float c[2][8][4];
#pragma unroll
    for (int i = 0; i < 2; i++)
#pragma unroll
        for (int j = 0; j < 8; j++)
#pragma unroll
            for (int v = 0; v < 4; v++) c[i][j][v] = 0.f;
    mma_tile(sb + NK_A, sb + NK_B, w, lane, c);
    store_f32(g_P, b1s, base, w, lane, c);
    __syncthreads();
    if (t < 64) build_B_W(smc, NK_B, W1 + 4096, t);
    __syncthreads();
#pragma unroll
    for (int i = 0; i < 2; i++)
#pragma unroll
        for (int j = 0; j < 8; j++)
#pragma unroll
            for (int v = 0; v < 4; v++) c[i][j][v] = 0.f;
    mma_tile(sb + NK_A, sb + NK_B, w, lane, c);
    store_f32(g_Q, (const float*)0, base, w, lane, c);
}

// ---------- fused residual(l) + nodePQ(l+1) ----------
__global__ void __launch_bounds__(128) k_residPQ(const float* __restrict__ g4, const float* __restrict__ be4,
                                                 int slot4,
                                                 const float* __restrict__ W1, const float* __restrict__ b1) {
    extern __shared__ char smc[];
    uint32_t sb = smem_u32(smc);
    float* al  = (float*)(smc + 16);
    float* be  = (float*)(smc + 16 + 256);
    float* b1s = (float*)(smc + 16 + 512);
    int t = threadIdx.x, w = t >> 5, lane = t & 31;
    int base = blockIdx.x*128, n = base + t;
    bnprep(al, be, slot4, 1.f/NN, g4, be4, t);
    if (t < 64) b1s[t] = b1[t];
    __syncthreads();
    if (n < NN) {
        float4* hp = (float4*)(g_h + (size_t)n*64);
        const float4* yp = (const float4*)(g_y4 + (size_t)n*64);
#pragma unroll
        for (int q = 0; q < 8; q++) {
            float4 h0 = hp[2*q], h1 = hp[2*q+1];
            float4 v0 = yp[2*q], v1 = yp[2*q+1];
            int c = q*8;
            h0.x += fmaxf(fmaf(al[c+0], v0.x, be[c+0]), 0.f);
            h0.y += fmaxf(fmaf(al[c+1], v0.y, be[c+1]), 0.f);
            h0.z += fmaxf(fmaf(al[c+2], v0.z, be[c+2]), 0.f);
            h0.w += fmaxf(fmaf(al[c+3], v0.w, be[c+3]), 0.f);
            h1.x += fmaxf(fmaf(al[c+4], v1.x, be[c+4]), 0.f);
            h1.y += fmaxf(fmaf(al[c+5], v1.y, be[c+5]), 0.f);
            h1.z += fmaxf(fmaf(al[c+6], v1.z, be[c+6]), 0.f);
            h1.w += fmaxf(fmaf(al[c+7], v1.w, be[c+7]), 0.f);
            hp[2*q] = h0; hp[2*q+1] = h1;
            __nv_bfloat162 p0 = __floats2bfloat162_rn(h0.x, h0.y);
            __nv_bfloat162 p1 = __floats2bfloat162_rn(h0.z, h0.w);
            __nv_bfloat162 p2 = __floats2bfloat162_rn(h1.x, h1.y);
            __nv_bfloat162 p3 = __floats2bfloat162_rn(h1.z, h1.w);
            uint4 o = { *(unsigned*)&p0, *(unsigned*)&p1, *(unsigned*)&p2, *(unsigned*)&p3 };
            *(uint4*)(smc + NK_A + SW128(t*128 + q*16)) = o;
        }
    } else {
        uint4 z = {0u,0u,0u,0u};
#pragma unroll
        for (int q = 0; q < 8; q++)
            *(uint4*)(smc + NK_A + SW128(t*128 + q*16)) = z;
    }
    if (t < 64) build_B_W(smc, NK_B, W1, t);
    __syncthreads();
    float c[2][8][4];
#pragma unroll
    for (int i = 0; i < 2; i++)
#pragma unroll
        for (int j = 0; j < 8; j++)
#pragma unroll
            for (int v = 0; v < 4; v++) c[i][j][v] = 0.f;
    mma_tile(sb + NK_A, sb + NK_B, w, lane, c);
    store_f32(g_P, b1s, base, w, lane, c);
    __syncthreads();
    if (t < 64) build_B_W(smc, NK_B, W1 + 4096, t);
    __syncthreads();
#pragma unroll
    for (int i = 0; i < 2; i++)
#pragma unroll
        for (int j = 0; j < 8; j++)
#pragma unroll
            for (int v = 0; v < 4; v++) c[i][j][v] = 0.f;
    mma_tile(sb + NK_A, sb + NK_B, w, lane, c);
    store_f32(g_Q, (const float*)0, base, w, lane, c);
}

// ---------- pass A: CSR-ordered, fp32 P/Q ----------
__global__ void __launch_bounds__(256) k_edgeA(const int* __restrict__ src, const int* __restrict__ dst,
                                               const float* __restrict__ ea, const float* __restrict__ W1, int slot) {
    __shared__ float Weas[256];
    __shared__ float ssum[64], ssq[64];
    int t = threadIdx.x;
    for (int i = t; i < 256; i += 256) Weas[i] = W1[8192 + i];
    if (t < 64) { ssum[t] = 0.f; ssq[t] = 0.f; }
    __syncthreads();
    int wg = (blockIdx.x*256 + t) >> 5, lane = t & 31;
    int nw = gridDim.x*8;
    int half = lane >> 4, c4 = (lane & 15) * 4;
    u64 wA0 = *(const u64*)(Weas + c4),       wB0 = *(const u64*)(Weas + c4 + 2);
    u64 wA1 = *(const u64*)(Weas + 64 + c4),  wB1 = *(const u64*)(Weas + 64 + c4 + 2);
    u64 wA2 = *(const u64*)(Weas + 128 + c4), wB2 = *(const u64*)(Weas + 128 + c4 + 2);
    u64 wA3 = *(const u64*)(Weas + 192 + c4), wB3 = *(const u64*)(Weas + 192 + c4 + 2);
    u64 spA = 0ull, spB = 0ull, qpA = 0ull, qpB = 0ull;
    for (int ib = wg*2; ib < NE; ib += nw*2) {
        int i = ib + half;
        if (i < NE) {
            int e = g_eidx[i];
            int s = src[e], d = dst[e];
            float4 ev = *(const float4*)(ea + (size_t)e*4);
            ulonglong2 Pv = *(const ulonglong2*)(g_P + (size_t)d*64 + c4);
            ulonglong2 Qv = *(const ulonglong2*)(g_Q + (size_t)s*64 + c4);
            u64 e0, e1, e2, e3;
            F2BCAST(e0, ev.x); F2BCAST(e1, ev.y); F2BCAST(e2, ev.z); F2BCAST(e3, ev.w);
            u64 yA; F2ADD(yA, Pv.x, Qv.x);
            F2FMA(yA, e0, wA0); F2FMA(yA, e1, wA1); F2FMA(yA, e2, wA2); F2FMA(yA, e3, wA3);
            u64 yB; F2ADD(yB, Pv.y, Qv.y);
            F2FMA(yB, e0, wB0); F2FMA(yB, e1, wB1); F2FMA(yB, e2, wB2); F2FMA(yB, e3, wB3);
            F2ADD(spA, spA, yA); F2FMA(qpA, yA, yA);
            F2ADD(spB, spB, yB); F2FMA(qpB, yB, yB);
            float a0, a1, b0, b1;
            F2UNPACK(a0, a1, yA); F2UNPACK(b0, b1, yB);
            __nv_bfloat162 h0 = __floats2bfloat162_rn(a0, a1);
            __nv_bfloat162 h1 = __floats2bfloat162_rn(b0, b1);
            uint2 o = { *(unsigned*)&h0, *(unsigned*)&h1 };
            *(uint2*)(g_y1 + (size_t)i*64 + c4) = o;
        }
    }
    float v0, v1, v2, v3, q0, q1, q2, q3;
    F2UNPACK(v0, v1, spA); F2UNPACK(v2, v3, spB);
    F2UNPACK(q0, q1, qpA); F2UNPACK(q2, q3, qpB);
    atomicAdd(&ssum[c4+0], v0); atomicAdd(&ssum[c4+1], v1);
    atomicAdd(&ssum[c4+2], v2); atomicAdd(&ssum[c4+3], v3);
    atomicAdd(&ssq[c4+0], q0); atomicAdd(&ssq[c4+1], q1);
    atomicAdd(&ssq[c4+2], q2); atomicAdd(&ssq[c4+3], q3);
    __syncthreads();
    if (t < 64) { atomicAdd(&g_sum[slot*64+t], ssum[t]); atomicAdd(&g_sq[slot*64+t], ssq[t]); }
}

// ---------- pass B: mma 128x64x64, register epilogue ----------
__global__ void __launch_bounds__(128) k_edgeB(const float* __restrict__ W2, const float* __restrict__ b2,
                                               const float* __restrict__ g1, const float* __restrict__ be1,
                                               int slot_in, int slot_out) {
    extern __shared__ char smc[];
    uint32_t sb = smem_u32(smc);
    float* al  = (float*)(smc + 16);
    float* be  = (float*)(smc + 16 + 256);
    float* b2s = (float*)(smc + 16 + 512);
    float* ssum = (float*)(smc + NK_RED);
    float* ssq  = ssum + 64;
    int t = threadIdx.x, w = t >> 5, lane = t & 31;
    int base = blockIdx.x * 128;
    bnprep(al, be, slot_in, 1.f/NE, g1, be1, t);
    if (t < 64) { b2s[t] = b2[t]; ssum[t] = 0.f; ssq[t] = 0.f; }
    __syncthreads();
    {
        const uint4* yp = (const uint4*)(g_y1 + (size_t)(base + t)*64);
#pragma unroll
        for (int q = 0; q < 8; q++) {
            uint4 u = yp[q];
            int c = q*8;
            float2 f0 = __bfloat1622float2(*(__nv_bfloat162*)&u.x);
            float2 f1 = __bfloat1622float2(*(__nv_bfloat162*)&u.y);
            float2 f2 = __bfloat1622float2(*(__nv_bfloat162*)&u.z);
            float2 f3 = __bfloat1622float2(*(__nv_bfloat162*)&u.w);
            float y0 = fmaxf(fmaf(al[c+0], f0.x, be[c+0]), 0.f);
            float y1v= fmaxf(fmaf(al[c+1], f0.y, be[c+1]), 0.f);
            float y2v= fmaxf(fmaf(al[c+2], f1.x, be[c+2]), 0.f);
            float y3v= fmaxf(fmaf(al[c+3], f1.y, be[c+3]), 0.f);
            float y4v= fmaxf(fmaf(al[c+4], f2.x, be[c+4]), 0.f);
            float y5 = fmaxf(fmaf(al[c+5], f2.y, be[c+5]), 0.f);
            float y6 = fmaxf(fmaf(al[c+6], f3.x, be[c+6]), 0.f);
            float y7 = fmaxf(fmaf(al[c+7], f3.y, be[c+7]), 0.f);
            __nv_bfloat162 p0 = __floats2bfloat162_rn(y0, y1v);
            __nv_bfloat162 p1 = __floats2bfloat162_rn(y2v, y3v);
            __nv_bfloat162 p2 = __floats2bfloat162_rn(y4v, y5);
            __nv_bfloat162 p3 = __floats2bfloat162_rn(y6, y7);
            uint4 o = { *(unsigned*)&p0, *(unsigned*)&p1, *(unsigned*)&p2, *(unsigned*)&p3 };
            *(uint4*)(smc + NK_A + SW128(t*128 + q*16)) = o;
        }
    }
    if (t < 64) build_B_W(smc, NK_B, W2, t);
    __syncthreads();
    float c[2][8][4];
#pragma unroll
    for (int i = 0; i < 2; i++)
#pragma unroll
        for (int j = 0; j < 8; j++)
#pragma unroll
            for (int v = 0; v < 4; v++) c[i][j][v] = 0.f;
    mma_tile(sb + NK_A, sb + NK_B, w, lane, c);
    int r = lane >> 2, cc = (lane & 3)*2;
#pragma unroll
    for (int nj = 0; nj < 8; nj++) {
        int col = nj*8 + cc;
        float b0 = b2s[col], b1 = b2s[col+1];
        float s0 = 0.f, s1 = 0.f, q0 = 0.f, q1 = 0.f;
#pragma unroll
        for (int mi = 0; mi < 2; mi++) {
            float v00 = c[mi][nj][0] + b0, v01 = c[mi][nj][1] + b1;
            float v10 = c[mi][nj][2] + b0, v11 = c[mi][nj][3] + b1;
            s0 += v00 + v10; s1 += v01 + v11;
            q0 += v00*v00 + v10*v10; q1 += v01*v01 + v11*v11;
            size_t row0 = (size_t)(base + w*32 + mi*16 + r);
            __nv_bfloat162 h0 = __floats2bfloat162_rn(v00, v01);
            __nv_bfloat162 h1 = __floats2bfloat162_rn(v10, v11);
            *(unsigned*)(g_y2 + row0*64 + col)       = *(unsigned*)&h0;
            *(unsigned*)(g_y2 + (row0 + 8)*64 + col) = *(unsigned*)&h1;
        }
#pragma unroll
        for (int off = 16; off >= 4; off >>= 1) {
            s0 += __shfl_down_sync(~0u, s0, off);
            s1 += __shfl_down_sync(~0u, s1, off);
            q0 += __shfl_down_sync(~0u, q0, off);
            q1 += __shfl_down_sync(~0u, q1, off);
        }
        if (lane < 4) {
            atomicAdd(&ssum[col], s0); atomicAdd(&ssum[col+1], s1);
            atomicAdd(&ssq[col],  q0); atomicAdd(&ssq[col+1],  q1);
        }
    }
    __syncthreads();
    if (t < 64) {
        atomicAdd(&g_sum[slot_out*64 + t], ssum[t]);
        atomicAdd(&g_sq [slot_out*64 + t], ssq[t]);
    }
}

// ---------- CSR aggregation: contiguous y2 rows ----------
__global__ void __launch_bounds__(256) k_aggr(const float* __restrict__ g2, const float* __restrict__ be2, int slot) {
    __shared__ float al[64], be[64];
    bnprep(al, be, slot, 1.f/NE, g2, be2, threadIdx.x);
    __syncthreads();
    int w = (blockIdx.x*256 + threadIdx.x) >> 5;
    if (w >= NN) return;
    int lane = threadIdx.x & 31;
    float alA = al[2*lane], beA = be[2*lane];
    float alB = al[2*lane+1], beB = be[2*lane+1];
    const __nv_bfloat162* y = (const __nv_bfloat162*)g_y2;
    float a0 = 0.f, a1 = 0.f;
    int s = g_rowstart[w], e = g_rowstart[w+1];
    for (int p = s; p < e; p++) {
        float2 v = __bfloat1622float2(y[(size_t)p*32 + lane]);
        a0 += fmaxf(fmaf(alA, v.x, beA), 0.f);
        a1 += fmaxf(fmaf(alB, v.y, beB), 0.f);
    }
    float2 o = {a0, a1};
    *(float2*)(g_aggr + (size_t)w*64 + 2*lane) = o;
}

// ---------- nodeU1 (mma, K=128) ----------
__global__ void __launch_bounds__(128) k_nodeU1(const float* __restrict__ W,
                                                const float* __restrict__ b3, int slot_out) {
    extern __shared__ char smc[];
    uint32_t sb = smem_u32(smc);
    float* b3s = (float*)(smc + 16);
    float* ssum = (float*)(smc + NK_RED);
    float* ssq  = ssum + 64;
    int t = threadIdx.x, w = t >> 5, lane = t & 31;
    int base = blockIdx.x*128, n = base + t;
    if (t < 64) { b3s[t] = b3[t]; ssum[t] = 0.f; ssq[t] = 0.f; }
    build_A_f32(smc, NK_A, g_h + (size_t)n*64, t, n < NN);
    if (t < 64) build_B_W(smc, NK_B, W, t);
    __syncthreads();
    float c[2][8][4];
#pragma unroll
    for (int i = 0; i < 2; i++)
#pragma unroll
        for (int j = 0; j < 8; j++)
#pragma unroll
            for (int v = 0; v < 4; v++) c[i][j][v] = 0.f;
    mma_tile(sb + NK_A, sb + NK_B, w, lane, c);
    __syncthreads();
    build_A_f32(smc, NK_A, g_aggr + (size_t)n*64, t, n < NN);
    if (t < 64) build_B_W(smc, NK_B, W + 4096, t);
    __syncthreads();
    mma_tile(sb + NK_A, sb + NK_B, w, lane, c);
    store_f32_stats(g_y3, b3s, base, w, lane, c, ssum, ssq);
    __syncthreads();
    if (t < 64) {
        atomicAdd(&g_sum[slot_out*64 + t], ssum[t]);
        atomicAdd(&g_sq [slot_out*64 + t], ssq[t]);
    }
}

// ---------- nodeU2 (mma) ----------
__global__ void __launch_bounds__(128) k_nodeU2(const float* __restrict__ W,
                                                const float* __restrict__ b4,
                                                const float* __restrict__ g3, const float* __restrict__ be3,
                                                int slot_in, int slot_out) {
    extern __shared__ char smc[];
    uint32_t sb = smem_u32(smc);
    float* al  = (float*)(smc + 16);
    float* be  = (float*)(smc + 16 + 256);
    float* b4s = (float*)(smc + 16 + 512);
    float* ssum = (float*)(smc + NK_RED);
    float* ssq  = ssum + 64;
    int t = threadIdx.x, w = t >> 5, lane = t & 31;
    int base = blockIdx.x*128, n = base + t;
    bnprep(al, be, slot_in, 1.f/NN, g3, be3, t);
    if (t < 64) { b4s[t] = b4[t]; ssum[t] = 0.f; ssq[t] = 0.f; }
    __syncthreads();
    if (n < NN) {
        const float4* yp = (const float4*)(g_y3 + (size_t)n*64);
#pragma unroll
        for (int q = 0; q < 8; q++) {
            float4 v0 = yp[2*q], v1 = yp[2*q+1];
            int c = q*8;
            float y0 = fmaxf(fmaf(al[c+0], v0.x, be[c+0]), 0.f);
            float y1v= fmaxf(fmaf(al[c+1], v0.y, be[c+1]), 0.f);
            float y2v= fmaxf(fmaf(al[c+2], v0.z, be[c+2]), 0.f);
            float y3v= fmaxf(fmaf(al[c+3], v0.w, be[c+3]), 0.f);
            float y4v= fmaxf(fmaf(al[c+4], v1.x, be[c+4]), 0.f);
            float y5 = fmaxf(fmaf(al[c+5], v1.y, be[c+5]), 0.f);
            float y6 = fmaxf(fmaf(al[c+6], v1.z, be[c+6]), 0.f);
            float y7 = fmaxf(fmaf(al[c+7], v1.w, be[c+7]), 0.f);
            __nv_bfloat162 p0 = __floats2bfloat162_rn(y0, y1v);
            __nv_bfloat162 p1 = __floats2bfloat162_rn(y2v, y3v);
            __nv_bfloat162 p2 = __floats2bfloat162_rn(y4v, y5);
            __nv_bfloat162 p3 = __floats2bfloat162_rn(y6, y7);
            uint4 o = { *(unsigned*)&p0, *(unsigned*)&p1, *(unsigned*)&p2, *(unsigned*)&p3 };
            *(uint4*)(smc + NK_A + SW128(t*128 + q*16)) = o;
        }
    } else {
        uint4 z = {0u,0u,0u,0u};
#pragma unroll
        for (int q = 0; q < 8; q++)
            *(uint4*)(smc + NK_A + SW128(t*128 + q*16)) = z;
    }
    if (t < 64) build_B_W(smc, NK_B, W, t);
    __syncthreads();
    float c[2][8][4];
#pragma unroll
    for (int i = 0; i < 2; i++)
#pragma unroll
        for (int j = 0; j < 8; j++)
#pragma unroll
            for (int v = 0; v < 4; v++) c[i][j][v] = 0.f;
    mma_tile(sb + NK_A, sb + NK_B, w, lane, c);
    store_f32_stats(g_y4, b4s, base, w, lane, c, ssum, ssq);
    __syncthreads();
    if (t < 64) {
        atomicAdd(&g_sum[slot_out*64 + t], ssum[t]);
        atomicAdd(&g_sq [slot_out*64 + t], ssq[t]);
    }
}

// ---------- residual (last layer only) ----------
__global__ void __launch_bounds__(256) k_resid(const float* __restrict__ g4, const float* __restrict__ be4, int slot) {
    __shared__ float al[64], be[64];
    bnprep(al, be, slot, 1.f/NN, g4, be4, threadIdx.x);
    __syncthreads();
    int i = blockIdx.x*256 + threadIdx.x;
    if (i < NN*D) {
        int c = i & 63;
        g_h[i] += fmaxf(fmaf(al[c], g_y4[i], be[c]), 0.f);
    }
}

// ---------- pooling ----------
__global__ void k_pool(const int* __restrict__ batch) {
    int w = blockIdx.x*8 + (threadIdx.x >> 5);
    int lane = threadIdx.x & 31;
    int n0 = w*64, n1 = min(n0 + 64, NN);
    if (n0 >= NN) return;
    float ax = 0.f, ay = 0.f, cnt = 0.f;
    int curg = batch[n0];
    for (int n = n0; n < n1; n++) {
        int g = batch[n];
        if (g != curg) {
            atomicAdd(&g_gsum[curg*64 + 2*lane], ax);
            atomicAdd(&g_gsum[curg*64 + 2*lane + 1], ay);
            if (lane == 0) atomicAdd(&g_gcnt[curg], cnt);
            ax = 0.f; ay = 0.f; cnt = 0.f; curg = g;
        }
        float2 v = *(const float2*)(g_h + n*64 + 2*lane);
        ax += v.x; ay += v.y; cnt += 1.f;
    }
    atomicAdd(&g_gsum[curg*64 + 2*lane], ax);
    atomicAdd(&g_gsum[curg*64 + 2*lane + 1], ay);
    if (lane == 0) atomicAdd(&g_gcnt[curg], cnt);
}

__global__ void k_pred(const float* __restrict__ pW, const float* __restrict__ pb,
                       float* __restrict__ out) {
    int g = threadIdx.x;
    if (g < NG) {
        float cnt = fmaxf(g_gcnt[g], 1.f);
        float acc = pb[0];
        for (int c = 0; c < D; c++) acc += g_gsum[g*64 + c] / cnt * pW[c];
        out[g] = acc;
    }
}

extern "C" void kernel_launch(void* const* d_in, const int* in_sizes, int n_in,
                              void* d_out, int out_size) {
    const float* x    = (const float*)d_in[0];
    const float* ea   = (const float*)d_in[1];
    const int*   ei   = (const int*)d_in[2];
    const int*   batch= (const int*)d_in[3];
    const float* linW = (const float*)d_in[4];
    const float* linb = (const float*)d_in[5];
    const float* mW1  = (const float*)d_in[6];
    const float* mb1  = (const float*)d_in[7];
    const float* mg1  = (const float*)d_in[8];
    const float* mbe1 = (const float*)d_in[9];
    const float* mW2  = (const float*)d_in[10];
    const float* mb2  = (const float*)d_in[11];
    const float* mg2  = (const float*)d_in[12];
    const float* mbe2 = (const float*)d_in[13];
    const float* uW1  = (const float*)d_in[14];
    const float* ub1  = (const float*)d_in[15];
    const float* ug1  = (const float*)d_in[16];
    const float* ube1 = (const float*)d_in[17];
    const float* uW2  = (const float*)d_in[18];
    const float* ub2  = (const float*)d_in[19];
    const float* ug2  = (const float*)d_in[20];
    const float* ube2 = (const float*)d_in[21];
    const float* pW   = (const float*)d_in[22];
    const float* pb   = (const float*)d_in[23];
    float* out = (float*)d_out;
    const int* src = ei;
    const int* dst = ei + NE;

    int nblk = (NN + 127) / 128;

    k_lin_in<<<(NN*4+255)/256, 256>>>(x, linW, linb);
    k_hist<<<(NE+255)/256, 256>>>(dst);
    k_scan<<<1, 1024>>>();
    k_nodePQ<<<nblk, 128, SM_NK>>>(mW1, mb1);
    k_scatter<<<(NE+255)/256, 256>>>(dst);

    for (int l = 0; l < 4; l++) {
        const float* W1 = mW1 + l*132*64;
        int s0 = l*4;
        k_edgeA<<<592, 256>>>(src, dst, ea, W1, s0);
        k_edgeB<<<NE/128, 128, SM_NK>>>(mW2 + l*4096, mb2 + l*64,
                                        mg1 + l*64, mbe1 + l*64, s0, s0+1);
        k_aggr<<<(NN*32+255)/256, 256>>>(mg2 + l*64, mbe2 + l*64, s0+1);
        k_nodeU1<<<nblk, 128, SM_NK>>>(uW1 + l*128*64, ub1 + l*64, s0+2);
        k_nodeU2<<<nblk, 128, SM_NK>>>(uW2 + l*4096, ub2 + l*64,
                                       ug1 + l*64, ube1 + l*64, s0+2, s0+3);
        if (l < 3) {
            k_residPQ<<<nblk, 128, SM_NK>>>(ug2 + l*64, ube2 + l*64, s0+3,
                                            mW1 + (l+1)*132*64, mb1 + (l+1)*64);
        } else {
            k_resid<<<(NN*D+255)/256, 256>>>(ug2 + l*64, ube2 + l*64, s0+3);
        }
    }
    k_pool<<<98, 256>>>(batch);
    k_pred<<<1, 32>>>(pW, pb, out);
}